// round 7
// baseline (speedup 1.0000x reference)
#include <cuda_runtime.h>
#include <math.h>
#include <stdint.h>

// Problem constants
#define BB   2
#define TT   2048
#define DD   2048
#define NH   16
#define NKV  4
#define HDm  128
#define MROWS (BB*TT)   // 4096

// Scratch
__device__ float g_q[BB*NH*TT*HDm];
__device__ float g_k[BB*NKV*TT*HDm];
__device__ float g_v[BB*NKV*TT*HDm];
__device__ float g_ctx[BB*TT*DD];
__device__ float g_rope[TT*128];       // [t][0..63]=cos, [t][64..127]=sin

// ---------------------------------------------------------------------------
// helpers
// ---------------------------------------------------------------------------
__device__ __forceinline__ uint32_t f2tf(float x) {
    uint32_t r; asm("cvt.rna.tf32.f32 %0, %1;" : "=r"(r) : "f"(x)); return r;
}
__device__ __forceinline__ float ex2(float x) {
    float y; asm("ex2.approx.f32 %0, %1;" : "=f"(y) : "f"(x)); return y;
}
__device__ __forceinline__ void mma_tf32(float c[4],
                                         uint32_t a0, uint32_t a1, uint32_t a2, uint32_t a3,
                                         uint32_t b0, uint32_t b1) {
    asm volatile(
        "mma.sync.aligned.m16n8k8.row.col.f32.tf32.tf32.f32 "
        "{%0,%1,%2,%3}, {%4,%5,%6,%7}, {%8,%9}, {%0,%1,%2,%3};\n"
        : "+f"(c[0]), "+f"(c[1]), "+f"(c[2]), "+f"(c[3])
        : "r"(a0), "r"(a1), "r"(a2), "r"(a3), "r"(b0), "r"(b1));
}

// ---------------------------------------------------------------------------
// 1xTF32 GEMM core: BM=BN=128, BK=16, 128 threads (4 warps), warp tile 64x64,
// double-buffered. A smem [m][k] stride 20, B smem [k][n] stride 136.
// ---------------------------------------------------------------------------
#define AST 20
#define BST 136
#define A_SZ (128 * AST)            // 2560 u32
#define B_SZ (16 * BST)             // 2176 u32
#define GBUF (A_SZ + B_SZ)          // 4736 u32
#define GEMM_SMEM_BYTES (2 * GBUF * 4)   // 37888

// Fused QKV projection: blockIdx.x selects {wq: 0..15, wk: 16..19, wv: 20..23}.
__global__ void __launch_bounds__(128, 2)
tqkv_k(const float* __restrict__ A,
       const float* __restrict__ wq, const float* __restrict__ wk,
       const float* __restrict__ wv,
       float* __restrict__ qo, float* __restrict__ ko, float* __restrict__ vo)
{
    extern __shared__ uint32_t gsm[];

    const int bx = blockIdx.x;
    const float* Bm;
    float* C;
    int N, n0, Hx;
    if (bx < 16)      { Bm = wq; C = qo; N = 2048; n0 = bx * 128;        Hx = 16; }
    else if (bx < 20) { Bm = wk; C = ko; N = 512;  n0 = (bx - 16) * 128; Hx = 4;  }
    else              { Bm = wv; C = vo; N = 512;  n0 = (bx - 20) * 128; Hx = 4;  }
    const int K = DD;

    const int tid = threadIdx.x;
    const int lane = tid & 31;
    const int wid = tid >> 5;
    const int warpM = wid & 1;
    const int warpN = wid >> 1;
    const int m0 = blockIdx.y * 128;

    const int arow = tid >> 2;        // 0..31 (+p*32)
    const int acol = (tid & 3) * 4;   // 0,4,8,12
    const int brow = tid >> 5;        // 0..3  (+p*4)
    const int bcol = (tid & 31) * 4;  // 0..124

    float acc[4][8][4];
#pragma unroll
    for (int i = 0; i < 4; i++)
#pragma unroll
        for (int j = 0; j < 8; j++)
#pragma unroll
            for (int r = 0; r < 4; r++) acc[i][j][r] = 0.f;

    float4 ra[4], rb[4];
#pragma unroll
    for (int p = 0; p < 4; p++) {
        ra[p] = *(const float4*)&A[(long)(m0 + arow + p * 32) * K + acol];
        rb[p] = *(const float4*)&Bm[(long)(brow + p * 4) * N + n0 + bcol];
    }

    const int NKT = K / 16;
    for (int kt = 0; kt < NKT; kt++) {
        uint32_t* As = gsm + (kt & 1) * GBUF;
        uint32_t* Bs = As + A_SZ;

#pragma unroll
        for (int p = 0; p < 4; p++) {
            int m = arow + p * 32;
            uint4 h;
            h.x = f2tf(ra[p].x); h.y = f2tf(ra[p].y);
            h.z = f2tf(ra[p].z); h.w = f2tf(ra[p].w);
            *(uint4*)&As[m * AST + acol] = h;
        }
#pragma unroll
        for (int p = 0; p < 4; p++) {
            int r = brow + p * 4;
            uint4 h;
            h.x = f2tf(rb[p].x); h.y = f2tf(rb[p].y);
            h.z = f2tf(rb[p].z); h.w = f2tf(rb[p].w);
            *(uint4*)&Bs[r * BST + bcol] = h;
        }
        __syncthreads();

        if (kt + 1 < NKT) {
            int k0 = (kt + 1) * 16;
#pragma unroll
            for (int p = 0; p < 4; p++) {
                ra[p] = *(const float4*)&A[(long)(m0 + arow + p * 32) * K + k0 + acol];
                rb[p] = *(const float4*)&Bm[(long)(k0 + brow + p * 4) * N + n0 + bcol];
            }
        }

#pragma unroll
        for (int ks = 0; ks < 2; ks++) {
            const int kk = ks * 8 + (lane & 3);
            uint32_t af[4][4];
#pragma unroll
            for (int mi = 0; mi < 4; mi++) {
                int m = warpM * 64 + mi * 16 + (lane >> 2);
                af[mi][0] = As[m * AST + kk];
                af[mi][1] = As[(m + 8) * AST + kk];
                af[mi][2] = As[m * AST + kk + 4];
                af[mi][3] = As[(m + 8) * AST + kk + 4];
            }
#pragma unroll
            for (int nt = 0; nt < 8; nt++) {
                int n = warpN * 64 + nt * 8 + (lane >> 2);
                uint32_t b0 = Bs[kk * BST + n];
                uint32_t b1 = Bs[(kk + 4) * BST + n];
#pragma unroll
                for (int mi = 0; mi < 4; mi++)
                    mma_tf32(acc[mi][nt], af[mi][0], af[mi][1], af[mi][2], af[mi][3], b0, b1);
            }
        }
        __syncthreads();
    }

#pragma unroll
    for (int mi = 0; mi < 4; mi++) {
        int r1 = m0 + warpM * 64 + mi * 16 + (lane >> 2);
        int r2 = r1 + 8;
#pragma unroll
        for (int nt = 0; nt < 8; nt++) {
            int c = n0 + warpN * 64 + nt * 8 + (lane & 3) * 2;
            int h = c >> 7, d = c & 127;
            int b1 = r1 >> 11, t1 = r1 & 2047;
            int b2 = r2 >> 11, t2 = r2 & 2047;
            *(float2*)&C[((long)(b1 * Hx + h) * TT + t1) * HDm + d] =
                make_float2(acc[mi][nt][0], acc[mi][nt][1]);
            *(float2*)&C[((long)(b2 * Hx + h) * TT + t2) * HDm + d] =
                make_float2(acc[mi][nt][2], acc[mi][nt][3]);
        }
    }
}

// Plain GEMM for output projection (row-major C).
__global__ void __launch_bounds__(128, 2)
tgemm_k(const float* __restrict__ A, const float* __restrict__ Bm,
        float* __restrict__ C, int M, int N, int K)
{
    extern __shared__ uint32_t gsm[];

    const int tid = threadIdx.x;
    const int lane = tid & 31;
    const int wid = tid >> 5;
    const int warpM = wid & 1;
    const int warpN = wid >> 1;
    const int m0 = blockIdx.y * 128;
    const int n0 = blockIdx.x * 128;

    const int arow = tid >> 2;
    const int acol = (tid & 3) * 4;
    const int brow = tid >> 5;
    const int bcol = (tid & 31) * 4;

    float acc[4][8][4];
#pragma unroll
    for (int i = 0; i < 4; i++)
#pragma unroll
        for (int j = 0; j < 8; j++)
#pragma unroll
            for (int r = 0; r < 4; r++) acc[i][j][r] = 0.f;

    float4 ra[4], rb[4];
#pragma unroll
    for (int p = 0; p < 4; p++) {
        ra[p] = *(const float4*)&A[(long)(m0 + arow + p * 32) * K + acol];
        rb[p] = *(const float4*)&Bm[(long)(brow + p * 4) * N + n0 + bcol];
    }

    const int NKT = K / 16;
    for (int kt = 0; kt < NKT; kt++) {
        uint32_t* As = gsm + (kt & 1) * GBUF;
        uint32_t* Bs = As + A_SZ;

#pragma unroll
        for (int p = 0; p < 4; p++) {
            int m = arow + p * 32;
            uint4 h;
            h.x = f2tf(ra[p].x); h.y = f2tf(ra[p].y);
            h.z = f2tf(ra[p].z); h.w = f2tf(ra[p].w);
            *(uint4*)&As[m * AST + acol] = h;
        }
#pragma unroll
        for (int p = 0; p < 4; p++) {
            int r = brow + p * 4;
            uint4 h;
            h.x = f2tf(rb[p].x); h.y = f2tf(rb[p].y);
            h.z = f2tf(rb[p].z); h.w = f2tf(rb[p].w);
            *(uint4*)&Bs[r * BST + bcol] = h;
        }
        __syncthreads();

        if (kt + 1 < NKT) {
            int k0 = (kt + 1) * 16;
#pragma unroll
            for (int p = 0; p < 4; p++) {
                ra[p] = *(const float4*)&A[(long)(m0 + arow + p * 32) * K + k0 + acol];
                rb[p] = *(const float4*)&Bm[(long)(k0 + brow + p * 4) * N + n0 + bcol];
            }
        }

#pragma unroll
        for (int ks = 0; ks < 2; ks++) {
            const int kk = ks * 8 + (lane & 3);
            uint32_t af[4][4];
#pragma unroll
            for (int mi = 0; mi < 4; mi++) {
                int m = warpM * 64 + mi * 16 + (lane >> 2);
                af[mi][0] = As[m * AST + kk];
                af[mi][1] = As[(m + 8) * AST + kk];
                af[mi][2] = As[m * AST + kk + 4];
                af[mi][3] = As[(m + 8) * AST + kk + 4];
            }
#pragma unroll
            for (int nt = 0; nt < 8; nt++) {
                int n = warpN * 64 + nt * 8 + (lane >> 2);
                uint32_t b0 = Bs[kk * BST + n];
                uint32_t b1 = Bs[(kk + 4) * BST + n];
#pragma unroll
                for (int mi = 0; mi < 4; mi++)
                    mma_tf32(acc[mi][nt], af[mi][0], af[mi][1], af[mi][2], af[mi][3], b0, b1);
            }
        }
        __syncthreads();
    }

#pragma unroll
    for (int mi = 0; mi < 4; mi++) {
        int r1 = m0 + warpM * 64 + mi * 16 + (lane >> 2);
        int r2 = r1 + 8;
#pragma unroll
        for (int nt = 0; nt < 8; nt++) {
            int c = n0 + warpN * 64 + nt * 8 + (lane & 3) * 2;
            *(float2*)&C[(long)r1 * N + c] = make_float2(acc[mi][nt][0], acc[mi][nt][1]);
            *(float2*)&C[(long)r2 * N + c] = make_float2(acc[mi][nt][2], acc[mi][nt][3]);
        }
    }
}

// ---------------------------------------------------------------------------
// RoPE cos/sin table
// ---------------------------------------------------------------------------
__global__ void rope_table_k(float* __restrict__ tab)
{
    int t = blockIdx.x;
    int j = threadIdx.x;
    float inv = exp2f(-(float)j * (13.287712379549449f / 64.0f));
    float ang = (float)t * inv;
    tab[t * 128 + j]      = cosf(ang);
    tab[t * 128 + 64 + j] = sinf(ang);
}

// ---------------------------------------------------------------------------
// Causal flash attention with FUSED RoPE: BQ=128, BK=32, 256 threads (8 warps).
// Warp w owns rows 16w..16w+15; Q frags + S + stats in registers.
// Q roped+scaled+tf32 at staging; K roped+tf32 at each tile store.
// ---------------------------------------------------------------------------
#define KST 132
#define VST 136
#define PST 36
#define FK_QS   (128 * KST)
#define FK_KOFF 0
#define FK_VOFF (2 * 32 * KST)
#define FK_POFF (FK_VOFF + 2 * 32 * VST)
#define FK_FLOATS_B (FK_POFF + 128 * PST)
#define FLASH_SMEM_FLOATS (FK_QS > FK_FLOATS_B ? FK_QS : FK_FLOATS_B)
#define FLASH_SMEM_BYTES  (FLASH_SMEM_FLOATS * 4)
#define SCALE_LOG2E 0.12751744709274227f   // (1/sqrt(128)) * log2(e)

__global__ void __launch_bounds__(256, 1)
flash_k(const float* __restrict__ Q, const float* __restrict__ Kp,
        const float* __restrict__ Vp, const float* __restrict__ tab,
        float* __restrict__ ctx)
{
    extern __shared__ float sm[];

    const int tid = threadIdx.x;
    const int lane = tid & 31;
    const int w = tid >> 5;
    const int quad = lane >> 2;
    const int j = lane & 3;
    const int qt = gridDim.x - 1 - blockIdx.x;
    const int h  = blockIdx.y;
    const int b  = blockIdx.z;
    const int hk = h >> 2;

    const float* qg = Q  + ((long)(b * NH  + h ) * TT + qt * 128) * HDm;
    const float* kg = Kp + ((long)(b * NKV + hk) * TT) * HDm;
    const float* vg = Vp + ((long)(b * NKV + hk) * TT) * HDm;

    // ---- Phase A: stage Q with fused RoPE + scale, tf32, into smem ----
    {
        float* Qs = sm;
        for (int i = tid; i < 128 * 16; i += 256) {
            int r = i >> 4;             // row 0..127
            int c4 = (i & 15) * 4;      // 0..60 (left half)
            int t = qt * 128 + r;
            float4 x1 = *(const float4*)&qg[(long)r * HDm + c4];
            float4 x2 = *(const float4*)&qg[(long)r * HDm + c4 + 64];
            float4 cs = *(const float4*)&tab[t * 128 + c4];
            float4 sn = *(const float4*)&tab[t * 128 + 64 + c4];
            float4 o1, o2;
            o1.x = __uint_as_float(f2tf((x1.x * cs.x - x2.x * sn.x) * SCALE_LOG2E));
            o1.y = __uint_as_float(f2tf((x1.y * cs.y - x2.y * sn.y) * SCALE_LOG2E));
            o1.z = __uint_as_float(f2tf((x1.z * cs.z - x2.z * sn.z) * SCALE_LOG2E));
            o1.w = __uint_as_float(f2tf((x1.w * cs.w - x2.w * sn.w) * SCALE_LOG2E));
            o2.x = __uint_as_float(f2tf((x2.x * cs.x + x1.x * sn.x) * SCALE_LOG2E));
            o2.y = __uint_as_float(f2tf((x2.y * cs.y + x1.y * sn.y) * SCALE_LOG2E));
            o2.z = __uint_as_float(f2tf((x2.z * cs.z + x1.z * sn.z) * SCALE_LOG2E));
            o2.w = __uint_as_float(f2tf((x2.w * cs.w + x1.w * sn.w) * SCALE_LOG2E));
            *(float4*)&Qs[r * KST + c4]      = o1;
            *(float4*)&Qs[r * KST + c4 + 64] = o2;
        }
    }
    __syncthreads();

    uint32_t qf[16][4];
    {
        const float* Qs = sm;
        int r = w * 16 + quad;
#pragma unroll
        for (int ks = 0; ks < 16; ks++) {
            int c = ks * 8 + j;
            qf[ks][0] = __float_as_uint(Qs[r * KST + c]);
            qf[ks][1] = __float_as_uint(Qs[(r + 8) * KST + c]);
            qf[ks][2] = __float_as_uint(Qs[r * KST + c + 4]);
            qf[ks][3] = __float_as_uint(Qs[(r + 8) * KST + c + 4]);
        }
    }
    __syncthreads();

    float* Ks = sm + FK_KOFF;
    float* Vs = sm + FK_VOFF;
    float* Ps = sm + FK_POFF;

    float oacc[16][4];
#pragma unroll
    for (int nt = 0; nt < 16; nt++)
#pragma unroll
        for (int r = 0; r < 4; r++) oacc[nt][r] = 0.f;

    float m0 = -INFINITY, m1 = -INFINITY, l0 = 0.f, l1 = 0.f;

    const int nkt = 4 * qt + 4;
    const int prow = w * 16 + quad;
    const int qi1 = qt * 128 + prow;
    const int qi2 = qi1 + 8;

    // K/V staging: 512 (row, left-col) slots per tile, 2 per thread.
    float4 rk1[2], rk2[2], rv1[2], rv2[2];
#pragma unroll
    for (int s = 0; s < 2; s++) {
        int idx = tid + s * 256;
        int r = idx >> 4, c4 = (idx & 15) * 4;
        rk1[s] = *(const float4*)&kg[(long)r * HDm + c4];
        rk2[s] = *(const float4*)&kg[(long)r * HDm + c4 + 64];
        rv1[s] = *(const float4*)&vg[(long)r * HDm + c4];
        rv2[s] = *(const float4*)&vg[(long)r * HDm + c4 + 64];
    }

    for (int kt = 0; kt < nkt; kt++) {
        float* Kb = Ks + (kt & 1) * 32 * KST;
        float* Vb = Vs + (kt & 1) * 32 * VST;

        // store staged tile: rope K, convert both
#pragma unroll
        for (int s = 0; s < 2; s++) {
            int idx = tid + s * 256;
            int r = idx >> 4, c4 = (idx & 15) * 4;
            int t = kt * 32 + r;
            float4 cs = *(const float4*)&tab[t * 128 + c4];
            float4 sn = *(const float4*)&tab[t * 128 + 64 + c4];
            float4 ko1, ko2, vo1, vo2;
            ko1.x = __uint_as_float(f2tf(rk1[s].x * cs.x - rk2[s].x * sn.x));
            ko1.y = __uint_as_float(f2tf(rk1[s].y * cs.y - rk2[s].y * sn.y));
            ko1.z = __uint_as_float(f2tf(rk1[s].z * cs.z - rk2[s].z * sn.z));
            ko1.w = __uint_as_float(f2tf(rk1[s].w * cs.w - rk2[s].w * sn.w));
            ko2.x = __uint_as_float(f2tf(rk2[s].x * cs.x + rk1[s].x * sn.x));
            ko2.y = __uint_as_float(f2tf(rk2[s].y * cs.y + rk1[s].y * sn.y));
            ko2.z = __uint_as_float(f2tf(rk2[s].z * cs.z + rk1[s].z * sn.z));
            ko2.w = __uint_as_float(f2tf(rk2[s].w * cs.w + rk1[s].w * sn.w));
            vo1.x = __uint_as_float(f2tf(rv1[s].x));
            vo1.y = __uint_as_float(f2tf(rv1[s].y));
            vo1.z = __uint_as_float(f2tf(rv1[s].z));
            vo1.w = __uint_as_float(f2tf(rv1[s].w));
            vo2.x = __uint_as_float(f2tf(rv2[s].x));
            vo2.y = __uint_as_float(f2tf(rv2[s].y));
            vo2.z = __uint_as_float(f2tf(rv2[s].z));
            vo2.w = __uint_as_float(f2tf(rv2[s].w));
            *(float4*)&Kb[r * KST + c4]      = ko1;
            *(float4*)&Kb[r * KST + c4 + 64] = ko2;
            *(float4*)&Vb[r * VST + c4]      = vo1;
            *(float4*)&Vb[r * VST + c4 + 64] = vo2;
        }
        __syncthreads();

        // prefetch next tile
        if (kt + 1 < nkt) {
#pragma unroll
            for (int s = 0; s < 2; s++) {
                int idx = tid + s * 256;
                int r = idx >> 4, c4 = (idx & 15) * 4;
                long g = ((long)((kt + 1) * 32 + r)) * HDm + c4;
                rk1[s] = *(const float4*)&kg[g];
                rk2[s] = *(const float4*)&kg[g + 64];
                rv1[s] = *(const float4*)&vg[g];
                rv2[s] = *(const float4*)&vg[g + 64];
            }
        }

        // ---- S = Q @ K^T ----
        float sf[4][4];
#pragma unroll
        for (int nt = 0; nt < 4; nt++)
#pragma unroll
            for (int r = 0; r < 4; r++) sf[nt][r] = 0.f;

#pragma unroll
        for (int ks = 0; ks < 16; ks++) {
            const int kk = ks * 8 + j;
#pragma unroll
            for (int nt = 0; nt < 4; nt++) {
                int key = nt * 8 + quad;
                uint32_t b0 = __float_as_uint(Kb[key * KST + kk]);
                uint32_t b1 = __float_as_uint(Kb[key * KST + kk + 4]);
                mma_tf32(sf[nt], qf[ks][0], qf[ks][1], qf[ks][2], qf[ks][3], b0, b1);
            }
        }

        // ---- causal mask (only diagonal-region tiles) ----
        if (kt >= 4 * qt) {
#pragma unroll
            for (int nt = 0; nt < 4; nt++) {
                int kj = kt * 32 + nt * 8 + 2 * j;
                if (kj     > qi1) sf[nt][0] = -INFINITY;
                if (kj + 1 > qi1) sf[nt][1] = -INFINITY;
                if (kj     > qi2) sf[nt][2] = -INFINITY;
                if (kj + 1 > qi2) sf[nt][3] = -INFINITY;
            }
        }

        // ---- online softmax (base 2), quad reduction ----
        float mx0 = -INFINITY, mx1 = -INFINITY;
#pragma unroll
        for (int nt = 0; nt < 4; nt++) {
            mx0 = fmaxf(mx0, fmaxf(sf[nt][0], sf[nt][1]));
            mx1 = fmaxf(mx1, fmaxf(sf[nt][2], sf[nt][3]));
        }
        mx0 = fmaxf(mx0, __shfl_xor_sync(0xffffffffu, mx0, 1));
        mx0 = fmaxf(mx0, __shfl_xor_sync(0xffffffffu, mx0, 2));
        mx1 = fmaxf(mx1, __shfl_xor_sync(0xffffffffu, mx1, 1));
        mx1 = fmaxf(mx1, __shfl_xor_sync(0xffffffffu, mx1, 2));

        float mn0 = fmaxf(m0, mx0);
        float mn1 = fmaxf(m1, mx1);
        float a0 = ex2(m0 - mn0);
        float a1 = ex2(m1 - mn1);
        m0 = mn0; m1 = mn1;

        float s0 = 0.f, s1 = 0.f;
#pragma unroll
        for (int nt = 0; nt < 4; nt++) {
            float p0 = __uint_as_float(f2tf(ex2(sf[nt][0] - mn0)));
            float p1 = __uint_as_float(f2tf(ex2(sf[nt][1] - mn0)));
            float p2 = __uint_as_float(f2tf(ex2(sf[nt][2] - mn1)));
            float p3 = __uint_as_float(f2tf(ex2(sf[nt][3] - mn1)));
            sf[nt][0] = p0; sf[nt][1] = p1; sf[nt][2] = p2; sf[nt][3] = p3;
            s0 += p0 + p1;
            s1 += p2 + p3;
        }
        s0 += __shfl_xor_sync(0xffffffffu, s0, 1);
        s0 += __shfl_xor_sync(0xffffffffu, s0, 2);
        s1 += __shfl_xor_sync(0xffffffffu, s1, 1);
        s1 += __shfl_xor_sync(0xffffffffu, s1, 2);
        l0 = l0 * a0 + s0;
        l1 = l1 * a1 + s1;

#pragma unroll
        for (int nt = 0; nt < 16; nt++) {
            oacc[nt][0] *= a0; oacc[nt][1] *= a0;
            oacc[nt][2] *= a1; oacc[nt][3] *= a1;
        }

        // ---- P -> warp-private smem pane ----
#pragma unroll
        for (int nt = 0; nt < 4; nt++) {
            int c = nt * 8 + 2 * j;
            *(float2*)&Ps[prow * PST + c]       = make_float2(sf[nt][0], sf[nt][1]);
            *(float2*)&Ps[(prow + 8) * PST + c] = make_float2(sf[nt][2], sf[nt][3]);
        }
        __syncwarp();

        // ---- O += P @ V ----
#pragma unroll
        for (int kb = 0; kb < 4; kb++) {
            int c = kb * 8 + j;
            uint32_t pa0 = __float_as_uint(Ps[prow * PST + c]);
            uint32_t pa1 = __float_as_uint(Ps[(prow + 8) * PST + c]);
            uint32_t pa2 = __float_as_uint(Ps[prow * PST + c + 4]);
            uint32_t pa3 = __float_as_uint(Ps[(prow + 8) * PST + c + 4]);
#pragma unroll
            for (int nt = 0; nt < 16; nt++) {
                int n = nt * 8 + quad;
                uint32_t b0 = __float_as_uint(Vb[(kb * 8 + j) * VST + n]);
                uint32_t b1 = __float_as_uint(Vb[(kb * 8 + j + 4) * VST + n]);
                mma_tf32(oacc[nt], pa0, pa1, pa2, pa3, b0, b1);
            }
        }
    }

    // ---- normalize + write to (B,T,D) ----
    float li0 = 1.0f / l0;
    float li1 = 1.0f / l1;
    int t1 = qt * 128 + prow;
    int t2 = t1 + 8;
#pragma unroll
    for (int nt = 0; nt < 16; nt++) {
        int n = h * HDm + nt * 8 + 2 * j;
        *(float2*)&ctx[((long)(b * TT + t1)) * DD + n] =
            make_float2(oacc[nt][0] * li0, oacc[nt][1] * li0);
        *(float2*)&ctx[((long)(b * TT + t2)) * DD + n] =
            make_float2(oacc[nt][2] * li1, oacc[nt][3] * li1);
    }
}

// ---------------------------------------------------------------------------
extern "C" void kernel_launch(void* const* d_in, const int* in_sizes, int n_in,
                              void* d_out, int out_size)
{
    const float* x  = (const float*)d_in[0];
    const float* wq = (const float*)d_in[1];
    const float* wk = (const float*)d_in[2];
    const float* wv = (const float*)d_in[3];
    const float* wo = (const float*)d_in[4];
    float* out = (float*)d_out;

    float *q, *k, *v, *ctx, *tab;
    cudaGetSymbolAddress((void**)&q,   g_q);
    cudaGetSymbolAddress((void**)&k,   g_k);
    cudaGetSymbolAddress((void**)&v,   g_v);
    cudaGetSymbolAddress((void**)&ctx, g_ctx);
    cudaGetSymbolAddress((void**)&tab, g_rope);

    cudaFuncSetAttribute(flash_k, cudaFuncAttributeMaxDynamicSharedMemorySize,
                         FLASH_SMEM_BYTES);

    rope_table_k<<<TT, 64>>>(tab);

    // Fused QKV projection (768 CTAs)
    tqkv_k<<<dim3(24, 32), 128, GEMM_SMEM_BYTES>>>(x, wq, wk, wv, q, k, v);

    // Flash attention with fused RoPE
    flash_k<<<dim3(TT / 128, NH, BB), 256, FLASH_SMEM_BYTES>>>(q, k, v, tab, ctx);

    // Output projection
    tgemm_k<<<dim3(16, 32), 128, GEMM_SMEM_BYTES>>>(ctx, wo, out, MROWS, DD, DD);
}

// round 8
// speedup vs baseline: 1.0400x; 1.0400x over previous
#include <cuda_runtime.h>
#include <math.h>
#include <stdint.h>

// Problem constants
#define BB   2
#define TT   2048
#define DD   2048
#define NH   16
#define NKV  4
#define HDm  128
#define MROWS (BB*TT)   // 4096

// Scratch
__device__ float g_q[BB*NH*TT*HDm];
__device__ float g_k[BB*NKV*TT*HDm];
__device__ float g_v[BB*NKV*TT*HDm];
__device__ float g_ctx[BB*TT*DD];
__device__ float g_rope[TT*128];       // [t][0..63]=cos, [t][64..127]=sin

// ---------------------------------------------------------------------------
// helpers
// ---------------------------------------------------------------------------
__device__ __forceinline__ uint32_t f2tf(float x) {
    uint32_t r; asm("cvt.rna.tf32.f32 %0, %1;" : "=r"(r) : "f"(x)); return r;
}
__device__ __forceinline__ float ex2(float x) {
    float y; asm("ex2.approx.f32 %0, %1;" : "=f"(y) : "f"(x)); return y;
}
__device__ __forceinline__ void mma_tf32(float c[4],
                                         uint32_t a0, uint32_t a1, uint32_t a2, uint32_t a3,
                                         uint32_t b0, uint32_t b1) {
    asm volatile(
        "mma.sync.aligned.m16n8k8.row.col.f32.tf32.tf32.f32 "
        "{%0,%1,%2,%3}, {%4,%5,%6,%7}, {%8,%9}, {%0,%1,%2,%3};\n"
        : "+f"(c[0]), "+f"(c[1]), "+f"(c[2]), "+f"(c[3])
        : "r"(a0), "r"(a1), "r"(a2), "r"(a3), "r"(b0), "r"(b1));
}

// ---------------------------------------------------------------------------
// 1xTF32 GEMM core (R5 config): BM=BN=128, BK=32, 128 threads (4 warps),
// warp tile 64x64, double-buffered. A smem [m][k] str 36, B smem [k][n] str 136.
// ---------------------------------------------------------------------------
#define AST 36
#define BST 136
#define A_SZ (128 * AST)            // 4608 u32
#define B_SZ (32 * BST)             // 4352 u32
#define GBUF (A_SZ + B_SZ)          // 8960 u32
#define GEMM_SMEM_BYTES (2 * GBUF * 4)   // 71680

// Fused QKV projection: blockIdx.x selects {wq: 0..15, wk: 16..19, wv: 20..23}.
__global__ void __launch_bounds__(128, 2)
tqkv_k(const float* __restrict__ A,
       const float* __restrict__ wq, const float* __restrict__ wk,
       const float* __restrict__ wv,
       float* __restrict__ qo, float* __restrict__ ko, float* __restrict__ vo)
{
    extern __shared__ uint32_t gsm[];

    const int bx = blockIdx.x;
    const float* Bm;
    float* C;
    int N, n0, Hx;
    if (bx < 16)      { Bm = wq; C = qo; N = 2048; n0 = bx * 128;        Hx = 16; }
    else if (bx < 20) { Bm = wk; C = ko; N = 512;  n0 = (bx - 16) * 128; Hx = 4;  }
    else              { Bm = wv; C = vo; N = 512;  n0 = (bx - 20) * 128; Hx = 4;  }
    const int K = DD;

    const int tid = threadIdx.x;
    const int lane = tid & 31;
    const int wid = tid >> 5;
    const int warpM = wid & 1;
    const int warpN = wid >> 1;
    const int m0 = blockIdx.y * 128;

    const int arow = tid >> 3;        // 0..15 (+p*16)
    const int acol = (tid & 7) * 4;   // 0..28
    const int brow = tid >> 5;        // 0..3  (+p*4)
    const int bcol = (tid & 31) * 4;  // 0..124

    float acc[4][8][4];
#pragma unroll
    for (int i = 0; i < 4; i++)
#pragma unroll
        for (int j = 0; j < 8; j++)
#pragma unroll
            for (int r = 0; r < 4; r++) acc[i][j][r] = 0.f;

    float4 ra[8], rb[8];
#pragma unroll
    for (int p = 0; p < 8; p++) {
        ra[p] = *(const float4*)&A[(long)(m0 + arow + p * 16) * K + acol];
        rb[p] = *(const float4*)&Bm[(long)(brow + p * 4) * N + n0 + bcol];
    }

    const int NKT = K / 32;
    for (int kt = 0; kt < NKT; kt++) {
        uint32_t* As = gsm + (kt & 1) * GBUF;
        uint32_t* Bs = As + A_SZ;

#pragma unroll
        for (int p = 0; p < 8; p++) {
            int m = arow + p * 16;
            uint4 h;
            h.x = f2tf(ra[p].x); h.y = f2tf(ra[p].y);
            h.z = f2tf(ra[p].z); h.w = f2tf(ra[p].w);
            *(uint4*)&As[m * AST + acol] = h;
        }
#pragma unroll
        for (int p = 0; p < 8; p++) {
            int r = brow + p * 4;
            uint4 h;
            h.x = f2tf(rb[p].x); h.y = f2tf(rb[p].y);
            h.z = f2tf(rb[p].z); h.w = f2tf(rb[p].w);
            *(uint4*)&Bs[r * BST + bcol] = h;
        }
        __syncthreads();

        if (kt + 1 < NKT) {
            int k0 = (kt + 1) * 32;
#pragma unroll
            for (int p = 0; p < 8; p++) {
                ra[p] = *(const float4*)&A[(long)(m0 + arow + p * 16) * K + k0 + acol];
                rb[p] = *(const float4*)&Bm[(long)(k0 + brow + p * 4) * N + n0 + bcol];
            }
        }

#pragma unroll
        for (int ks = 0; ks < 4; ks++) {
            const int kk = ks * 8 + (lane & 3);
            uint32_t af[4][4];
#pragma unroll
            for (int mi = 0; mi < 4; mi++) {
                int m = warpM * 64 + mi * 16 + (lane >> 2);
                af[mi][0] = As[m * AST + kk];
                af[mi][1] = As[(m + 8) * AST + kk];
                af[mi][2] = As[m * AST + kk + 4];
                af[mi][3] = As[(m + 8) * AST + kk + 4];
            }
#pragma unroll
            for (int nt = 0; nt < 8; nt++) {
                int n = warpN * 64 + nt * 8 + (lane >> 2);
                uint32_t b0 = Bs[kk * BST + n];
                uint32_t b1 = Bs[(kk + 4) * BST + n];
#pragma unroll
                for (int mi = 0; mi < 4; mi++)
                    mma_tf32(acc[mi][nt], af[mi][0], af[mi][1], af[mi][2], af[mi][3], b0, b1);
            }
        }
        __syncthreads();
    }

#pragma unroll
    for (int mi = 0; mi < 4; mi++) {
        int r1 = m0 + warpM * 64 + mi * 16 + (lane >> 2);
        int r2 = r1 + 8;
#pragma unroll
        for (int nt = 0; nt < 8; nt++) {
            int c = n0 + warpN * 64 + nt * 8 + (lane & 3) * 2;
            int h = c >> 7, d = c & 127;
            int b1 = r1 >> 11, t1 = r1 & 2047;
            int b2 = r2 >> 11, t2 = r2 & 2047;
            *(float2*)&C[((long)(b1 * Hx + h) * TT + t1) * HDm + d] =
                make_float2(acc[mi][nt][0], acc[mi][nt][1]);
            *(float2*)&C[((long)(b2 * Hx + h) * TT + t2) * HDm + d] =
                make_float2(acc[mi][nt][2], acc[mi][nt][3]);
        }
    }
}

// Plain GEMM for output projection (row-major C), same R5 core.
__global__ void __launch_bounds__(128, 2)
tgemm_k(const float* __restrict__ A, const float* __restrict__ Bm,
        float* __restrict__ C, int M, int N, int K)
{
    extern __shared__ uint32_t gsm[];

    const int tid = threadIdx.x;
    const int lane = tid & 31;
    const int wid = tid >> 5;
    const int warpM = wid & 1;
    const int warpN = wid >> 1;
    const int m0 = blockIdx.y * 128;
    const int n0 = blockIdx.x * 128;

    const int arow = tid >> 3;
    const int acol = (tid & 7) * 4;
    const int brow = tid >> 5;
    const int bcol = (tid & 31) * 4;

    float acc[4][8][4];
#pragma unroll
    for (int i = 0; i < 4; i++)
#pragma unroll
        for (int j = 0; j < 8; j++)
#pragma unroll
            for (int r = 0; r < 4; r++) acc[i][j][r] = 0.f;

    float4 ra[8], rb[8];
#pragma unroll
    for (int p = 0; p < 8; p++) {
        ra[p] = *(const float4*)&A[(long)(m0 + arow + p * 16) * K + acol];
        rb[p] = *(const float4*)&Bm[(long)(brow + p * 4) * N + n0 + bcol];
    }

    const int NKT = K / 32;
    for (int kt = 0; kt < NKT; kt++) {
        uint32_t* As = gsm + (kt & 1) * GBUF;
        uint32_t* Bs = As + A_SZ;

#pragma unroll
        for (int p = 0; p < 8; p++) {
            int m = arow + p * 16;
            uint4 h;
            h.x = f2tf(ra[p].x); h.y = f2tf(ra[p].y);
            h.z = f2tf(ra[p].z); h.w = f2tf(ra[p].w);
            *(uint4*)&As[m * AST + acol] = h;
        }
#pragma unroll
        for (int p = 0; p < 8; p++) {
            int r = brow + p * 4;
            uint4 h;
            h.x = f2tf(rb[p].x); h.y = f2tf(rb[p].y);
            h.z = f2tf(rb[p].z); h.w = f2tf(rb[p].w);
            *(uint4*)&Bs[r * BST + bcol] = h;
        }
        __syncthreads();

        if (kt + 1 < NKT) {
            int k0 = (kt + 1) * 32;
#pragma unroll
            for (int p = 0; p < 8; p++) {
                ra[p] = *(const float4*)&A[(long)(m0 + arow + p * 16) * K + k0 + acol];
                rb[p] = *(const float4*)&Bm[(long)(k0 + brow + p * 4) * N + n0 + bcol];
            }
        }

#pragma unroll
        for (int ks = 0; ks < 4; ks++) {
            const int kk = ks * 8 + (lane & 3);
            uint32_t af[4][4];
#pragma unroll
            for (int mi = 0; mi < 4; mi++) {
                int m = warpM * 64 + mi * 16 + (lane >> 2);
                af[mi][0] = As[m * AST + kk];
                af[mi][1] = As[(m + 8) * AST + kk];
                af[mi][2] = As[m * AST + kk + 4];
                af[mi][3] = As[(m + 8) * AST + kk + 4];
            }
#pragma unroll
            for (int nt = 0; nt < 8; nt++) {
                int n = warpN * 64 + nt * 8 + (lane >> 2);
                uint32_t b0 = Bs[kk * BST + n];
                uint32_t b1 = Bs[(kk + 4) * BST + n];
#pragma unroll
                for (int mi = 0; mi < 4; mi++)
                    mma_tf32(acc[mi][nt], af[mi][0], af[mi][1], af[mi][2], af[mi][3], b0, b1);
            }
        }
        __syncthreads();
    }

#pragma unroll
    for (int mi = 0; mi < 4; mi++) {
        int r1 = m0 + warpM * 64 + mi * 16 + (lane >> 2);
        int r2 = r1 + 8;
#pragma unroll
        for (int nt = 0; nt < 8; nt++) {
            int c = n0 + warpN * 64 + nt * 8 + (lane & 3) * 2;
            *(float2*)&C[(long)r1 * N + c] = make_float2(acc[mi][nt][0], acc[mi][nt][1]);
            *(float2*)&C[(long)r2 * N + c] = make_float2(acc[mi][nt][2], acc[mi][nt][3]);
        }
    }
}

// ---------------------------------------------------------------------------
// RoPE cos/sin table
// ---------------------------------------------------------------------------
__global__ void rope_table_k(float* __restrict__ tab)
{
    int t = blockIdx.x;
    int j = threadIdx.x;
    float inv = exp2f(-(float)j * (13.287712379549449f / 64.0f));
    float ang = (float)t * inv;
    tab[t * 128 + j]      = cosf(ang);
    tab[t * 128 + 64 + j] = sinf(ang);
}

// ---------------------------------------------------------------------------
// Causal flash attention with FUSED RoPE (R7 version): BQ=128, BK=32,
// 256 threads (8 warps). Q frags + S + stats in registers.
// ---------------------------------------------------------------------------
#define KST 132
#define VST 136
#define PST 36
#define FK_QS   (128 * KST)
#define FK_KOFF 0
#define FK_VOFF (2 * 32 * KST)
#define FK_POFF (FK_VOFF + 2 * 32 * VST)
#define FK_FLOATS_B (FK_POFF + 128 * PST)
#define FLASH_SMEM_FLOATS (FK_QS > FK_FLOATS_B ? FK_QS : FK_FLOATS_B)
#define FLASH_SMEM_BYTES  (FLASH_SMEM_FLOATS * 4)
#define SCALE_LOG2E 0.12751744709274227f   // (1/sqrt(128)) * log2(e)

__global__ void __launch_bounds__(256, 1)
flash_k(const float* __restrict__ Q, const float* __restrict__ Kp,
        const float* __restrict__ Vp, const float* __restrict__ tab,
        float* __restrict__ ctx)
{
    extern __shared__ float sm[];

    const int tid = threadIdx.x;
    const int lane = tid & 31;
    const int w = tid >> 5;
    const int quad = lane >> 2;
    const int j = lane & 3;
    const int qt = gridDim.x - 1 - blockIdx.x;
    const int h  = blockIdx.y;
    const int b  = blockIdx.z;
    const int hk = h >> 2;

    const float* qg = Q  + ((long)(b * NH  + h ) * TT + qt * 128) * HDm;
    const float* kg = Kp + ((long)(b * NKV + hk) * TT) * HDm;
    const float* vg = Vp + ((long)(b * NKV + hk) * TT) * HDm;

    // ---- Phase A: stage Q with fused RoPE + scale, tf32, into smem ----
    {
        float* Qs = sm;
        for (int i = tid; i < 128 * 16; i += 256) {
            int r = i >> 4;
            int c4 = (i & 15) * 4;
            int t = qt * 128 + r;
            float4 x1 = *(const float4*)&qg[(long)r * HDm + c4];
            float4 x2 = *(const float4*)&qg[(long)r * HDm + c4 + 64];
            float4 cs = *(const float4*)&tab[t * 128 + c4];
            float4 sn = *(const float4*)&tab[t * 128 + 64 + c4];
            float4 o1, o2;
            o1.x = __uint_as_float(f2tf((x1.x * cs.x - x2.x * sn.x) * SCALE_LOG2E));
            o1.y = __uint_as_float(f2tf((x1.y * cs.y - x2.y * sn.y) * SCALE_LOG2E));
            o1.z = __uint_as_float(f2tf((x1.z * cs.z - x2.z * sn.z) * SCALE_LOG2E));
            o1.w = __uint_as_float(f2tf((x1.w * cs.w - x2.w * sn.w) * SCALE_LOG2E));
            o2.x = __uint_as_float(f2tf((x2.x * cs.x + x1.x * sn.x) * SCALE_LOG2E));
            o2.y = __uint_as_float(f2tf((x2.y * cs.y + x1.y * sn.y) * SCALE_LOG2E));
            o2.z = __uint_as_float(f2tf((x2.z * cs.z + x1.z * sn.z) * SCALE_LOG2E));
            o2.w = __uint_as_float(f2tf((x2.w * cs.w + x1.w * sn.w) * SCALE_LOG2E));
            *(float4*)&Qs[r * KST + c4]      = o1;
            *(float4*)&Qs[r * KST + c4 + 64] = o2;
        }
    }
    __syncthreads();

    uint32_t qf[16][4];
    {
        const float* Qs = sm;
        int r = w * 16 + quad;
#pragma unroll
        for (int ks = 0; ks < 16; ks++) {
            int c = ks * 8 + j;
            qf[ks][0] = __float_as_uint(Qs[r * KST + c]);
            qf[ks][1] = __float_as_uint(Qs[(r + 8) * KST + c]);
            qf[ks][2] = __float_as_uint(Qs[r * KST + c + 4]);
            qf[ks][3] = __float_as_uint(Qs[(r + 8) * KST + c + 4]);
        }
    }
    __syncthreads();

    float* Ks = sm + FK_KOFF;
    float* Vs = sm + FK_VOFF;
    float* Ps = sm + FK_POFF;

    float oacc[16][4];
#pragma unroll
    for (int nt = 0; nt < 16; nt++)
#pragma unroll
        for (int r = 0; r < 4; r++) oacc[nt][r] = 0.f;

    float m0 = -INFINITY, m1 = -INFINITY, l0 = 0.f, l1 = 0.f;

    const int nkt = 4 * qt + 4;
    const int prow = w * 16 + quad;
    const int qi1 = qt * 128 + prow;
    const int qi2 = qi1 + 8;

    float4 rk1[2], rk2[2], rv1[2], rv2[2];
#pragma unroll
    for (int s = 0; s < 2; s++) {
        int idx = tid + s * 256;
        int r = idx >> 4, c4 = (idx & 15) * 4;
        rk1[s] = *(const float4*)&kg[(long)r * HDm + c4];
        rk2[s] = *(const float4*)&kg[(long)r * HDm + c4 + 64];
        rv1[s] = *(const float4*)&vg[(long)r * HDm + c4];
        rv2[s] = *(const float4*)&vg[(long)r * HDm + c4 + 64];
    }

    for (int kt = 0; kt < nkt; kt++) {
        float* Kb = Ks + (kt & 1) * 32 * KST;
        float* Vb = Vs + (kt & 1) * 32 * VST;

#pragma unroll
        for (int s = 0; s < 2; s++) {
            int idx = tid + s * 256;
            int r = idx >> 4, c4 = (idx & 15) * 4;
            int t = kt * 32 + r;
            float4 cs = *(const float4*)&tab[t * 128 + c4];
            float4 sn = *(const float4*)&tab[t * 128 + 64 + c4];
            float4 ko1, ko2, vo1, vo2;
            ko1.x = __uint_as_float(f2tf(rk1[s].x * cs.x - rk2[s].x * sn.x));
            ko1.y = __uint_as_float(f2tf(rk1[s].y * cs.y - rk2[s].y * sn.y));
            ko1.z = __uint_as_float(f2tf(rk1[s].z * cs.z - rk2[s].z * sn.z));
            ko1.w = __uint_as_float(f2tf(rk1[s].w * cs.w - rk2[s].w * sn.w));
            ko2.x = __uint_as_float(f2tf(rk2[s].x * cs.x + rk1[s].x * sn.x));
            ko2.y = __uint_as_float(f2tf(rk2[s].y * cs.y + rk1[s].y * sn.y));
            ko2.z = __uint_as_float(f2tf(rk2[s].z * cs.z + rk1[s].z * sn.z));
            ko2.w = __uint_as_float(f2tf(rk2[s].w * cs.w + rk1[s].w * sn.w));
            vo1.x = __uint_as_float(f2tf(rv1[s].x));
            vo1.y = __uint_as_float(f2tf(rv1[s].y));
            vo1.z = __uint_as_float(f2tf(rv1[s].z));
            vo1.w = __uint_as_float(f2tf(rv1[s].w));
            vo2.x = __uint_as_float(f2tf(rv2[s].x));
            vo2.y = __uint_as_float(f2tf(rv2[s].y));
            vo2.z = __uint_as_float(f2tf(rv2[s].z));
            vo2.w = __uint_as_float(f2tf(rv2[s].w));
            *(float4*)&Kb[r * KST + c4]      = ko1;
            *(float4*)&Kb[r * KST + c4 + 64] = ko2;
            *(float4*)&Vb[r * VST + c4]      = vo1;
            *(float4*)&Vb[r * VST + c4 + 64] = vo2;
        }
        __syncthreads();

        if (kt + 1 < nkt) {
#pragma unroll
            for (int s = 0; s < 2; s++) {
                int idx = tid + s * 256;
                int r = idx >> 4, c4 = (idx & 15) * 4;
                long g = ((long)((kt + 1) * 32 + r)) * HDm + c4;
                rk1[s] = *(const float4*)&kg[g];
                rk2[s] = *(const float4*)&kg[g + 64];
                rv1[s] = *(const float4*)&vg[g];
                rv2[s] = *(const float4*)&vg[g + 64];
            }
        }

        // ---- S = Q @ K^T ----
        float sf[4][4];
#pragma unroll
        for (int nt = 0; nt < 4; nt++)
#pragma unroll
            for (int r = 0; r < 4; r++) sf[nt][r] = 0.f;

#pragma unroll
        for (int ks = 0; ks < 16; ks++) {
            const int kk = ks * 8 + j;
#pragma unroll
            for (int nt = 0; nt < 4; nt++) {
                int key = nt * 8 + quad;
                uint32_t b0 = __float_as_uint(Kb[key * KST + kk]);
                uint32_t b1 = __float_as_uint(Kb[key * KST + kk + 4]);
                mma_tf32(sf[nt], qf[ks][0], qf[ks][1], qf[ks][2], qf[ks][3], b0, b1);
            }
        }

        if (kt >= 4 * qt) {
#pragma unroll
            for (int nt = 0; nt < 4; nt++) {
                int kj = kt * 32 + nt * 8 + 2 * j;
                if (kj     > qi1) sf[nt][0] = -INFINITY;
                if (kj + 1 > qi1) sf[nt][1] = -INFINITY;
                if (kj     > qi2) sf[nt][2] = -INFINITY;
                if (kj + 1 > qi2) sf[nt][3] = -INFINITY;
            }
        }

        // ---- online softmax (base 2), quad reduction ----
        float mx0 = -INFINITY, mx1 = -INFINITY;
#pragma unroll
        for (int nt = 0; nt < 4; nt++) {
            mx0 = fmaxf(mx0, fmaxf(sf[nt][0], sf[nt][1]));
            mx1 = fmaxf(mx1, fmaxf(sf[nt][2], sf[nt][3]));
        }
        mx0 = fmaxf(mx0, __shfl_xor_sync(0xffffffffu, mx0, 1));
        mx0 = fmaxf(mx0, __shfl_xor_sync(0xffffffffu, mx0, 2));
        mx1 = fmaxf(mx1, __shfl_xor_sync(0xffffffffu, mx1, 1));
        mx1 = fmaxf(mx1, __shfl_xor_sync(0xffffffffu, mx1, 2));

        float mn0 = fmaxf(m0, mx0);
        float mn1 = fmaxf(m1, mx1);
        float a0 = ex2(m0 - mn0);
        float a1 = ex2(m1 - mn1);
        m0 = mn0; m1 = mn1;

        float s0 = 0.f, s1 = 0.f;
#pragma unroll
        for (int nt = 0; nt < 4; nt++) {
            float p0 = __uint_as_float(f2tf(ex2(sf[nt][0] - mn0)));
            float p1 = __uint_as_float(f2tf(ex2(sf[nt][1] - mn0)));
            float p2 = __uint_as_float(f2tf(ex2(sf[nt][2] - mn1)));
            float p3 = __uint_as_float(f2tf(ex2(sf[nt][3] - mn1)));
            sf[nt][0] = p0; sf[nt][1] = p1; sf[nt][2] = p2; sf[nt][3] = p3;
            s0 += p0 + p1;
            s1 += p2 + p3;
        }
        s0 += __shfl_xor_sync(0xffffffffu, s0, 1);
        s0 += __shfl_xor_sync(0xffffffffu, s0, 2);
        s1 += __shfl_xor_sync(0xffffffffu, s1, 1);
        s1 += __shfl_xor_sync(0xffffffffu, s1, 2);
        l0 = l0 * a0 + s0;
        l1 = l1 * a1 + s1;

#pragma unroll
        for (int nt = 0; nt < 16; nt++) {
            oacc[nt][0] *= a0; oacc[nt][1] *= a0;
            oacc[nt][2] *= a1; oacc[nt][3] *= a1;
        }

        // ---- P -> warp-private smem pane ----
#pragma unroll
        for (int nt = 0; nt < 4; nt++) {
            int c = nt * 8 + 2 * j;
            *(float2*)&Ps[prow * PST + c]       = make_float2(sf[nt][0], sf[nt][1]);
            *(float2*)&Ps[(prow + 8) * PST + c] = make_float2(sf[nt][2], sf[nt][3]);
        }
        __syncwarp();

        // ---- O += P @ V ----
#pragma unroll
        for (int kb = 0; kb < 4; kb++) {
            int c = kb * 8 + j;
            uint32_t pa0 = __float_as_uint(Ps[prow * PST + c]);
            uint32_t pa1 = __float_as_uint(Ps[(prow + 8) * PST + c]);
            uint32_t pa2 = __float_as_uint(Ps[prow * PST + c + 4]);
            uint32_t pa3 = __float_as_uint(Ps[(prow + 8) * PST + c + 4]);
#pragma unroll
            for (int nt = 0; nt < 16; nt++) {
                int n = nt * 8 + quad;
                uint32_t b0 = __float_as_uint(Vb[(kb * 8 + j) * VST + n]);
                uint32_t b1 = __float_as_uint(Vb[(kb * 8 + j + 4) * VST + n]);
                mma_tf32(oacc[nt], pa0, pa1, pa2, pa3, b0, b1);
            }
        }
    }

    // ---- normalize + write to (B,T,D) ----
    float li0 = 1.0f / l0;
    float li1 = 1.0f / l1;
    int t1 = qt * 128 + prow;
    int t2 = t1 + 8;
#pragma unroll
    for (int nt = 0; nt < 16; nt++) {
        int n = h * HDm + nt * 8 + 2 * j;
        *(float2*)&ctx[((long)(b * TT + t1)) * DD + n] =
            make_float2(oacc[nt][0] * li0, oacc[nt][1] * li0);
        *(float2*)&ctx[((long)(b * TT + t2)) * DD + n] =
            make_float2(oacc[nt][2] * li1, oacc[nt][3] * li1);
    }
}

// ---------------------------------------------------------------------------
extern "C" void kernel_launch(void* const* d_in, const int* in_sizes, int n_in,
                              void* d_out, int out_size)
{
    const float* x  = (const float*)d_in[0];
    const float* wq = (const float*)d_in[1];
    const float* wk = (const float*)d_in[2];
    const float* wv = (const float*)d_in[3];
    const float* wo = (const float*)d_in[4];
    float* out = (float*)d_out;

    float *q, *k, *v, *ctx, *tab;
    cudaGetSymbolAddress((void**)&q,   g_q);
    cudaGetSymbolAddress((void**)&k,   g_k);
    cudaGetSymbolAddress((void**)&v,   g_v);
    cudaGetSymbolAddress((void**)&ctx, g_ctx);
    cudaGetSymbolAddress((void**)&tab, g_rope);

    cudaFuncSetAttribute(tqkv_k, cudaFuncAttributeMaxDynamicSharedMemorySize,
                         GEMM_SMEM_BYTES);
    cudaFuncSetAttribute(tgemm_k, cudaFuncAttributeMaxDynamicSharedMemorySize,
                         GEMM_SMEM_BYTES);
    cudaFuncSetAttribute(flash_k, cudaFuncAttributeMaxDynamicSharedMemorySize,
                         FLASH_SMEM_BYTES);

    rope_table_k<<<TT, 64>>>(tab);

    // Fused QKV projection (768 CTAs, BK=32)
    tqkv_k<<<dim3(24, 32), 128, GEMM_SMEM_BYTES>>>(x, wq, wk, wv, q, k, v);

    // Flash attention with fused RoPE
    flash_k<<<dim3(TT / 128, NH, BB), 256, FLASH_SMEM_BYTES>>>(q, k, v, tab, ctx);

    // Output projection (BK=32)
    tgemm_k<<<dim3(16, 32), 128, GEMM_SMEM_BYTES>>>(ctx, wo, out, MROWS, DD, DD);
}